// round 1
// baseline (speedup 1.0000x reference)
#include <cuda_runtime.h>

#define D     512
#define LSEQ  8192
#define BATCH 8
#define NROWS (BATCH*LSEQ)   // 65536
#define TM    64
#define TE    128
#define KC    32
#define NECHUNK (D/TE)       // 4
#define NKSTAGE (D/KC)       // 16

// Output layout (float32, tuple order):
#define OFF_COMP 0ull
#define OFF_MASK 33554432ull            // B*L*D
#define OFF_BH   (OFF_MASK + 65536ull)
#define OFF_P    (OFF_BH   + 65536ull)
#define OFF_PC   (OFF_P    + 65536ull)
#define OFF_LOSS (OFF_PC   + 65536ull)  // 33816576

// scratch (static device arrays: no allocation)
__device__ float g_num[NROWS];
__device__ float g_nq[NROWS];
__device__ float g_nkp[NROWS];
__device__ int   g_pos[NROWS];
__device__ int   g_cnt[BATCH];
__device__ float g_bsum[BATCH * 2];   // per-batch {sum b_hard, sum p}

__device__ __forceinline__ float2 ffma2(float2 a, float2 b, float2 c) {
    unsigned long long au = *reinterpret_cast<unsigned long long*>(&a);
    unsigned long long bu = *reinterpret_cast<unsigned long long*>(&b);
    unsigned long long cu = *reinterpret_cast<unsigned long long*>(&c);
    unsigned long long du;
    asm("fma.rn.f32x2 %0, %1, %2, %3;" : "=l"(du) : "l"(au), "l"(bu), "l"(cu));
    return *reinterpret_cast<float2*>(&du);
}

// ---------------------------------------------------------------------------
// Kernel 1: fused Q/K GEMM + per-row reductions.
// For each global row r: g_num[r] = q[r]·k[r-1], g_nq[r]=|q[r]|^2, g_nkp[r]=|k[r-1]|^2
// (row -1 clamped to 0; its value is irrelevant — p is forced to 1 at l==0).
// ---------------------------------------------------------------------------
__global__ __launch_bounds__(256, 2)
void gemm_cos_kernel(const float* __restrict__ x,
                     const float* __restrict__ Wq,
                     const float* __restrict__ Wk) {
    __shared__ float xs [KC][68];    // xs[kk][j], j=0..64 -> global row m0-1+j
    __shared__ float wqs[KC][132];   // wqs[kk][e]
    __shared__ float wks[KC][132];

    const int tid = threadIdx.x;
    const int tx  = tid & 15;        // e-group: cols tx*8 .. tx*8+7
    const int ty  = tid >> 4;        // row-group: rows ty*4 .. ty*4+3
    const int m0  = blockIdx.x * TM;

    float sum_num[4] = {0.f,0.f,0.f,0.f};
    float sum_nq [4] = {0.f,0.f,0.f,0.f};
    float sum_nk [4] = {0.f,0.f,0.f,0.f};

    for (int ec = 0; ec < NECHUNK; ec++) {
        const int e0 = ec * TE;
        float2 accq[4][4], acck[4][4];
        #pragma unroll
        for (int i = 0; i < 4; i++)
            #pragma unroll
            for (int j = 0; j < 4; j++) {
                accq[i][j] = make_float2(0.f, 0.f);
                acck[i][j] = make_float2(0.f, 0.f);
            }

        for (int ks = 0; ks < NKSTAGE; ks++) {
            const int k0 = ks * KC;
            __syncthreads();
            // load x tile: 65 rows x 32 cols, transposed into xs[kk][j]
            {
                const int jj  = tid >> 3;
                const int kkb = (tid & 7) * 4;
                #pragma unroll
                for (int it = 0; it < 3; it++) {
                    int j = jj + it * 32;
                    if (j < 65) {
                        int gr = m0 - 1 + j; if (gr < 0) gr = 0;
                        float4 v = *reinterpret_cast<const float4*>(
                            &x[(size_t)gr * D + k0 + kkb]);
                        xs[kkb+0][j] = v.x; xs[kkb+1][j] = v.y;
                        xs[kkb+2][j] = v.z; xs[kkb+3][j] = v.w;
                    }
                }
            }
            // load W tiles: 128 e x 32 k, transposed into w*s[kk][e]
            {
                const int eb  = tid >> 3;
                const int kkb = (tid & 7) * 4;
                #pragma unroll
                for (int it = 0; it < 4; it++) {
                    int e = eb + it * 32;
                    float4 vq = *reinterpret_cast<const float4*>(
                        &Wq[(size_t)(e0 + e) * D + k0 + kkb]);
                    float4 vk = *reinterpret_cast<const float4*>(
                        &Wk[(size_t)(e0 + e) * D + k0 + kkb]);
                    wqs[kkb+0][e] = vq.x; wqs[kkb+1][e] = vq.y;
                    wqs[kkb+2][e] = vq.z; wqs[kkb+3][e] = vq.w;
                    wks[kkb+0][e] = vk.x; wks[kkb+1][e] = vk.y;
                    wks[kkb+2][e] = vk.z; wks[kkb+3][e] = vk.w;
                }
            }
            __syncthreads();

            #pragma unroll
            for (int kk = 0; kk < KC; kk++) {
                float4 xk4 = *reinterpret_cast<const float4*>(&xs[kk][ty * 4]);
                float  xh  = xs[kk][ty * 4 + 4];
                float xv[5] = {xk4.x, xk4.y, xk4.z, xk4.w, xh};

                float4 wq0 = *reinterpret_cast<const float4*>(&wqs[kk][tx * 8]);
                float4 wq1 = *reinterpret_cast<const float4*>(&wqs[kk][tx * 8 + 4]);
                float4 wk0 = *reinterpret_cast<const float4*>(&wks[kk][tx * 8]);
                float4 wk1 = *reinterpret_cast<const float4*>(&wks[kk][tx * 8 + 4]);
                float2 wqp[4] = {{wq0.x,wq0.y},{wq0.z,wq0.w},{wq1.x,wq1.y},{wq1.z,wq1.w}};
                float2 wkp[4] = {{wk0.x,wk0.y},{wk0.z,wk0.w},{wk1.x,wk1.y},{wk1.z,wk1.w}};

                #pragma unroll
                for (int i = 0; i < 4; i++) {
                    float2 aq = make_float2(xv[i+1], xv[i+1]); // q row m0+ty*4+i
                    float2 ak = make_float2(xv[i],   xv[i]);   // k row m0+ty*4+i-1
                    #pragma unroll
                    for (int jp = 0; jp < 4; jp++) {
                        accq[i][jp] = ffma2(aq, wqp[jp], accq[i][jp]);
                        acck[i][jp] = ffma2(ak, wkp[jp], acck[i][jp]);
                    }
                }
            }
        }

        // reduce this e-chunk into per-row scalars (butterfly over the 16 tx lanes)
        #pragma unroll
        for (int i = 0; i < 4; i++) {
            float pn = 0.f, pq = 0.f, pk = 0.f;
            #pragma unroll
            for (int jp = 0; jp < 4; jp++) {
                pn += accq[i][jp].x * acck[i][jp].x + accq[i][jp].y * acck[i][jp].y;
                pq += accq[i][jp].x * accq[i][jp].x + accq[i][jp].y * accq[i][jp].y;
                pk += acck[i][jp].x * acck[i][jp].x + acck[i][jp].y * acck[i][jp].y;
            }
            #pragma unroll
            for (int m = 1; m < 16; m <<= 1) {
                pn += __shfl_xor_sync(0xffffffffu, pn, m);
                pq += __shfl_xor_sync(0xffffffffu, pq, m);
                pk += __shfl_xor_sync(0xffffffffu, pk, m);
            }
            sum_num[i] += pn; sum_nq[i] += pq; sum_nk[i] += pk;
        }
    }

    if (tx == 0) {
        #pragma unroll
        for (int i = 0; i < 4; i++) {
            int r = m0 + ty * 4 + i;
            g_num[r] = sum_num[i];
            g_nq [r] = sum_nq [i];
            g_nkp[r] = sum_nk [i];
        }
    }
}

// ---------------------------------------------------------------------------
// Kernel 2: per-batch p / b_hard / prefix-scan positions / batch sums.
// One block per batch, 256 threads, 32 elements per thread (sequential).
// ---------------------------------------------------------------------------
__global__ __launch_bounds__(256)
void scan_kernel(float* __restrict__ out) {
    const int b   = blockIdx.x;
    const int tid = threadIdx.x;
    const int PER = LSEQ / 256;            // 32
    const int base = b * LSEQ + tid * PER;

    __shared__ int   sInt[256];
    __shared__ float sF  [256];

    float pv[32];
    unsigned bits = 0;
    int   localsum = 0;
    float psum = 0.f;

    #pragma unroll
    for (int u = 0; u < PER; u++) {
        int r = base + u;
        float num = g_num[r], nq = g_nq[r], nk = g_nkp[r];
        float cs = num * rsqrtf(nq * nk);
        float p  = 0.5f * (1.0f - cs);
        p = fminf(fmaxf(p, 0.0f), 1.0f);
        if ((r & (LSEQ - 1)) == 0) p = 1.0f;     // l == 0
        pv[u] = p;
        int h = (p >= 0.5f) ? 1 : 0;
        bits |= ((unsigned)h) << u;
        localsum += h;
        psum += p;
    }

    // block-wide inclusive scan (Hillis-Steele) of localsum
    sInt[tid] = localsum;
    __syncthreads();
    for (int off = 1; off < 256; off <<= 1) {
        int v = (tid >= off) ? sInt[tid - off] : 0;
        __syncthreads();
        sInt[tid] += v;
        __syncthreads();
    }
    int excl  = sInt[tid] - localsum;
    int total = sInt[255];

    // write p, b_hard, positions
    int run = excl;
    #pragma unroll
    for (int u = 0; u < PER; u++) {
        int r = base + u;
        float p = pv[u];
        int h = (bits >> u) & 1;
        out[OFF_P  + r] = p;
        out[OFF_BH + r] = h ? 1.0f : 0.0f;
        g_pos[r] = h ? run : -1;
        run += h;
    }

    // reduce sum(p)
    sF[tid] = psum;
    __syncthreads();
    for (int off = 128; off > 0; off >>= 1) {
        if (tid < off) sF[tid] += sF[tid + off];
        __syncthreads();
    }
    if (tid == 0) {
        g_cnt[b] = total;
        g_bsum[b * 2 + 0] = (float)total;
        g_bsum[b * 2 + 1] = sF[0];
    }
}

// ---------------------------------------------------------------------------
// Kernel 3: scatter selected rows into compressed, zero-fill tail, mask, p_comp.
// One block (128 threads) per source/dest row index r = b*LSEQ + l.
// ---------------------------------------------------------------------------
__global__ __launch_bounds__(128)
void scatter_kernel(const float* __restrict__ x, float* __restrict__ out) {
    const int r   = blockIdx.x;
    const int b   = r >> 13;           // / LSEQ
    const int l   = r & (LSEQ - 1);
    const int tid = threadIdx.x;       // 128 threads x float4 = 512 floats

    int pos = g_pos[r];
    if (pos >= 0) {
        float4 v = reinterpret_cast<const float4*>(x + (size_t)r * D)[tid];
        size_t dst = (size_t)(b * LSEQ + pos) * D;
        reinterpret_cast<float4*>(out + OFF_COMP + dst)[tid] = v;
        if (tid == 0) out[OFF_PC + b * LSEQ + pos] = out[OFF_P + r];
    }
    int cnt = g_cnt[b];
    if (l >= cnt) {
        reinterpret_cast<float4*>(out + OFF_COMP + (size_t)r * D)[tid] =
            make_float4(0.f, 0.f, 0.f, 0.f);
        if (tid == 0) { out[OFF_PC + r] = 0.f; out[OFF_MASK + r] = 0.f; }
    } else if (tid == 0) {
        out[OFF_MASK + r] = 1.0f;
    }
}

// ---------------------------------------------------------------------------
// Kernel 4: ratio loss scalar.
// ---------------------------------------------------------------------------
__global__ void loss_kernel(float* __restrict__ out) {
    float F = 0.f, G = 0.f;
    for (int b = 0; b < BATCH; b++) { F += g_bsum[b*2+0]; G += g_bsum[b*2+1]; }
    F /= (float)NROWS;
    G /= (float)NROWS;
    const float N = 6.0f;   // 1 / TARGET_RATIO
    float loss = N / (N - 1.0f) * ((N - 1.0f) * F * G + (1.0f - F) * (1.0f - G));
    out[OFF_LOSS] = loss;
}

extern "C" void kernel_launch(void* const* d_in, const int* in_sizes, int n_in,
                              void* d_out, int out_size) {
    const float* x  = (const float*)d_in[0];
    const float* Wq = (const float*)d_in[1];
    const float* Wk = (const float*)d_in[2];
    float* out = (float*)d_out;

    gemm_cos_kernel<<<NROWS / TM, 256>>>(x, Wq, Wk);
    scan_kernel<<<BATCH, 256>>>(out);
    scatter_kernel<<<NROWS, 128>>>(x, out);
    loss_kernel<<<1, 1>>>(out);
}

// round 2
// speedup vs baseline: 1.6149x; 1.6149x over previous
#include <cuda_runtime.h>

#define D     512
#define LSEQ  8192
#define BATCH 8
#define NROWS (BATCH*LSEQ)   // 65536
#define TM    64
#define TE    128
#define KC    32
#define NECHUNK (D/TE)       // 4
#define NKSTAGE (D/KC)       // 16

// Output layout (float32, tuple order):
#define OFF_COMP 0ull
#define OFF_MASK 33554432ull            // B*L*D
#define OFF_BH   (OFF_MASK + 65536ull)
#define OFF_P    (OFF_BH   + 65536ull)
#define OFF_PC   (OFF_P    + 65536ull)
#define OFF_LOSS (OFF_PC   + 65536ull)  // 33816576

// scratch (static device arrays: no allocation)
__device__ float g_num[NROWS];
__device__ float g_nq[NROWS];
__device__ float g_nkp[NROWS];
__device__ int   g_pos[NROWS];
__device__ int   g_cnt[BATCH];
__device__ float g_bsum[BATCH * 2];   // per-batch {sum b_hard, sum p}

__device__ __forceinline__ float2 ffma2(float2 a, float2 b, float2 c) {
    unsigned long long au = *reinterpret_cast<unsigned long long*>(&a);
    unsigned long long bu = *reinterpret_cast<unsigned long long*>(&b);
    unsigned long long cu = *reinterpret_cast<unsigned long long*>(&c);
    unsigned long long du;
    asm("fma.rn.f32x2 %0, %1, %2, %3;" : "=l"(du) : "l"(au), "l"(bu), "l"(cu));
    return *reinterpret_cast<float2*>(&du);
}

// ---------------------------------------------------------------------------
// Kernel 1: fused Q/K GEMM + per-row reductions.
// For each global row r: g_num[r] = q[r]·k[r-1], g_nq[r]=|q[r]|^2, g_nkp[r]=|k[r-1]|^2
// (row -1 clamped to 0; its value is irrelevant — p is forced to 1 at l==0).
// ---------------------------------------------------------------------------
__global__ __launch_bounds__(256, 2)
void gemm_cos_kernel(const float* __restrict__ x,
                     const float* __restrict__ Wq,
                     const float* __restrict__ Wk) {
    __shared__ float xs [KC][68];    // xs[kk][j], j=0..64 -> global row m0-1+j
    __shared__ float wqs[KC][132];   // wqs[kk][e]
    __shared__ float wks[KC][132];

    const int tid = threadIdx.x;
    const int tx  = tid & 15;        // e-group: cols tx*8 .. tx*8+7
    const int ty  = tid >> 4;        // row-group: rows ty*4 .. ty*4+3
    const int m0  = blockIdx.x * TM;

    float sum_num[4] = {0.f,0.f,0.f,0.f};
    float sum_nq [4] = {0.f,0.f,0.f,0.f};
    float sum_nk [4] = {0.f,0.f,0.f,0.f};

    for (int ec = 0; ec < NECHUNK; ec++) {
        const int e0 = ec * TE;
        float2 accq[4][4], acck[4][4];
        #pragma unroll
        for (int i = 0; i < 4; i++)
            #pragma unroll
            for (int j = 0; j < 4; j++) {
                accq[i][j] = make_float2(0.f, 0.f);
                acck[i][j] = make_float2(0.f, 0.f);
            }

        for (int ks = 0; ks < NKSTAGE; ks++) {
            const int k0 = ks * KC;
            __syncthreads();
            // load x tile: 65 rows x 32 cols, transposed into xs[kk][j]
            {
                const int jj  = tid >> 3;
                const int kkb = (tid & 7) * 4;
                #pragma unroll
                for (int it = 0; it < 3; it++) {
                    int j = jj + it * 32;
                    if (j < 65) {
                        int gr = m0 - 1 + j; if (gr < 0) gr = 0;
                        float4 v = *reinterpret_cast<const float4*>(
                            &x[(size_t)gr * D + k0 + kkb]);
                        xs[kkb+0][j] = v.x; xs[kkb+1][j] = v.y;
                        xs[kkb+2][j] = v.z; xs[kkb+3][j] = v.w;
                    }
                }
            }
            // load W tiles: 128 e x 32 k, transposed into w*s[kk][e]
            {
                const int eb  = tid >> 3;
                const int kkb = (tid & 7) * 4;
                #pragma unroll
                for (int it = 0; it < 4; it++) {
                    int e = eb + it * 32;
                    float4 vq = *reinterpret_cast<const float4*>(
                        &Wq[(size_t)(e0 + e) * D + k0 + kkb]);
                    float4 vk = *reinterpret_cast<const float4*>(
                        &Wk[(size_t)(e0 + e) * D + k0 + kkb]);
                    wqs[kkb+0][e] = vq.x; wqs[kkb+1][e] = vq.y;
                    wqs[kkb+2][e] = vq.z; wqs[kkb+3][e] = vq.w;
                    wks[kkb+0][e] = vk.x; wks[kkb+1][e] = vk.y;
                    wks[kkb+2][e] = vk.z; wks[kkb+3][e] = vk.w;
                }
            }
            __syncthreads();

            #pragma unroll
            for (int kk = 0; kk < KC; kk++) {
                float4 xk4 = *reinterpret_cast<const float4*>(&xs[kk][ty * 4]);
                float  xh  = xs[kk][ty * 4 + 4];
                float xv[5] = {xk4.x, xk4.y, xk4.z, xk4.w, xh};

                float4 wq0 = *reinterpret_cast<const float4*>(&wqs[kk][tx * 8]);
                float4 wq1 = *reinterpret_cast<const float4*>(&wqs[kk][tx * 8 + 4]);
                float4 wk0 = *reinterpret_cast<const float4*>(&wks[kk][tx * 8]);
                float4 wk1 = *reinterpret_cast<const float4*>(&wks[kk][tx * 8 + 4]);
                float2 wqp[4] = {{wq0.x,wq0.y},{wq0.z,wq0.w},{wq1.x,wq1.y},{wq1.z,wq1.w}};
                float2 wkp[4] = {{wk0.x,wk0.y},{wk0.z,wk0.w},{wk1.x,wk1.y},{wk1.z,wk1.w}};

                #pragma unroll
                for (int i = 0; i < 4; i++) {
                    float2 aq = make_float2(xv[i+1], xv[i+1]); // q row m0+ty*4+i
                    float2 ak = make_float2(xv[i],   xv[i]);   // k row m0+ty*4+i-1
                    #pragma unroll
                    for (int jp = 0; jp < 4; jp++) {
                        accq[i][jp] = ffma2(aq, wqp[jp], accq[i][jp]);
                        acck[i][jp] = ffma2(ak, wkp[jp], acck[i][jp]);
                    }
                }
            }
        }

        // reduce this e-chunk into per-row scalars (butterfly over the 16 tx lanes)
        #pragma unroll
        for (int i = 0; i < 4; i++) {
            float pn = 0.f, pq = 0.f, pk = 0.f;
            #pragma unroll
            for (int jp = 0; jp < 4; jp++) {
                pn += accq[i][jp].x * acck[i][jp].x + accq[i][jp].y * acck[i][jp].y;
                pq += accq[i][jp].x * accq[i][jp].x + accq[i][jp].y * accq[i][jp].y;
                pk += acck[i][jp].x * acck[i][jp].x + acck[i][jp].y * acck[i][jp].y;
            }
            #pragma unroll
            for (int m = 1; m < 16; m <<= 1) {
                pn += __shfl_xor_sync(0xffffffffu, pn, m);
                pq += __shfl_xor_sync(0xffffffffu, pq, m);
                pk += __shfl_xor_sync(0xffffffffu, pk, m);
            }
            sum_num[i] += pn; sum_nq[i] += pq; sum_nk[i] += pk;
        }
    }

    if (tx == 0) {
        #pragma unroll
        for (int i = 0; i < 4; i++) {
            int r = m0 + ty * 4 + i;
            g_num[r] = sum_num[i];
            g_nq [r] = sum_nq [i];
            g_nkp[r] = sum_nk [i];
        }
    }
}

// ---------------------------------------------------------------------------
// Kernel 2: per-batch p / b_hard / prefix-scan positions / batch sums.
// One block per batch, 256 threads, 32 elements per thread (sequential).
// ---------------------------------------------------------------------------
__global__ __launch_bounds__(256)
void scan_kernel(float* __restrict__ out) {
    const int b   = blockIdx.x;
    const int tid = threadIdx.x;
    const int PER = LSEQ / 256;            // 32
    const int base = b * LSEQ + tid * PER;

    __shared__ int   sInt[256];
    __shared__ float sF  [256];

    float pv[32];
    unsigned bits = 0;
    int   localsum = 0;
    float psum = 0.f;

    #pragma unroll
    for (int u = 0; u < PER; u++) {
        int r = base + u;
        float num = g_num[r], nq = g_nq[r], nk = g_nkp[r];
        float cs = num * rsqrtf(nq * nk);
        float p  = 0.5f * (1.0f - cs);
        p = fminf(fmaxf(p, 0.0f), 1.0f);
        if ((r & (LSEQ - 1)) == 0) p = 1.0f;     // l == 0
        pv[u] = p;
        int h = (p >= 0.5f) ? 1 : 0;
        bits |= ((unsigned)h) << u;
        localsum += h;
        psum += p;
    }

    // block-wide inclusive scan (Hillis-Steele) of localsum
    sInt[tid] = localsum;
    __syncthreads();
    for (int off = 1; off < 256; off <<= 1) {
        int v = (tid >= off) ? sInt[tid - off] : 0;
        __syncthreads();
        sInt[tid] += v;
        __syncthreads();
    }
    int excl  = sInt[tid] - localsum;
    int total = sInt[255];

    // write p, b_hard, positions
    int run = excl;
    #pragma unroll
    for (int u = 0; u < PER; u++) {
        int r = base + u;
        float p = pv[u];
        int h = (bits >> u) & 1;
        out[OFF_P  + r] = p;
        out[OFF_BH + r] = h ? 1.0f : 0.0f;
        g_pos[r] = h ? run : -1;
        run += h;
    }

    // reduce sum(p)
    sF[tid] = psum;
    __syncthreads();
    for (int off = 128; off > 0; off >>= 1) {
        if (tid < off) sF[tid] += sF[tid + off];
        __syncthreads();
    }
    if (tid == 0) {
        g_cnt[b] = total;
        g_bsum[b * 2 + 0] = (float)total;
        g_bsum[b * 2 + 1] = sF[0];
    }
}

// ---------------------------------------------------------------------------
// Kernel 3: scatter selected rows into compressed, zero-fill tail, mask, p_comp.
// One block (128 threads) per source/dest row index r = b*LSEQ + l.
// ---------------------------------------------------------------------------
__global__ __launch_bounds__(128)
void scatter_kernel(const float* __restrict__ x, float* __restrict__ out) {
    const int r   = blockIdx.x;
    const int b   = r >> 13;           // / LSEQ
    const int l   = r & (LSEQ - 1);
    const int tid = threadIdx.x;       // 128 threads x float4 = 512 floats

    int pos = g_pos[r];
    if (pos >= 0) {
        float4 v = reinterpret_cast<const float4*>(x + (size_t)r * D)[tid];
        size_t dst = (size_t)(b * LSEQ + pos) * D;
        reinterpret_cast<float4*>(out + OFF_COMP + dst)[tid] = v;
        if (tid == 0) out[OFF_PC + b * LSEQ + pos] = out[OFF_P + r];
    }
    int cnt = g_cnt[b];
    if (l >= cnt) {
        reinterpret_cast<float4*>(out + OFF_COMP + (size_t)r * D)[tid] =
            make_float4(0.f, 0.f, 0.f, 0.f);
        if (tid == 0) { out[OFF_PC + r] = 0.f; out[OFF_MASK + r] = 0.f; }
    } else if (tid == 0) {
        out[OFF_MASK + r] = 1.0f;
    }
}

// ---------------------------------------------------------------------------
// Kernel 4: ratio loss scalar.
// ---------------------------------------------------------------------------
__global__ void loss_kernel(float* __restrict__ out) {
    float F = 0.f, G = 0.f;
    for (int b = 0; b < BATCH; b++) { F += g_bsum[b*2+0]; G += g_bsum[b*2+1]; }
    F /= (float)NROWS;
    G /= (float)NROWS;
    const float N = 6.0f;   // 1 / TARGET_RATIO
    float loss = N / (N - 1.0f) * ((N - 1.0f) * F * G + (1.0f - F) * (1.0f - G));
    out[OFF_LOSS] = loss;
}

extern "C" void kernel_launch(void* const* d_in, const int* in_sizes, int n_in,
                              void* d_out, int out_size) {
    const float* x  = (const float*)d_in[0];
    const float* Wq = (const float*)d_in[1];
    const float* Wk = (const float*)d_in[2];
    float* out = (float*)d_out;

    gemm_cos_kernel<<<NROWS / TM, 256>>>(x, Wq, Wk);
    scan_kernel<<<BATCH, 256>>>(out);
    scatter_kernel<<<NROWS, 128>>>(x, out);
    loss_kernel<<<1, 1>>>(out);
}

// round 9
// speedup vs baseline: 5.6735x; 3.5133x over previous
#include <cuda_runtime.h>
#include <cstdint>

#define D     512
#define LSEQ  8192
#define BATCH 8
#define NROWS (BATCH*LSEQ)   // 65536

// Output layout (float32, tuple order):
#define OFF_COMP 0ull
#define OFF_MASK 33554432ull            // B*L*D
#define OFF_BH   (OFF_MASK + 65536ull)
#define OFF_P    (OFF_BH   + 65536ull)
#define OFF_PC   (OFF_P    + 65536ull)
#define OFF_LOSS (OFF_PC   + 65536ull)

#define FLAG_CAP 8192

// GEMM tiling
#define SA        20                  // smem row stride in floats (pad for banks)
#define KC        16
#define NSTG      (D/KC)              // 32 k-stages
#define SLOT_F    (128*SA*2)          // floats per slot (A + B)
#define DYN_SMEM  (3*SLOT_F*4)        // 61440 bytes

// cvt work size
#define NX4   ((size_t)NROWS * D / 4)          // 8388608 float4 of x
#define NW4   (2u * 512u * 512u / 4u)          // 131072 float4 of W
#define CVT_TOTAL (NX4 + NW4)                  // 8519680
#define CVT_BLOCKS 33280                       // * 256 == 8519680 exactly

// ---- scratch (static device arrays: no allocation) ----
__device__ float g_xc[(size_t)NROWS * D];     // tf32-rounded x   (128 MB)
__device__ float g_Wc[1024 * D];              // tf32-rounded [Wq;Wk] (2 MB)
__device__ float g_Q[(size_t)NROWS * D];      // 128 MB
__device__ float g_K[(size_t)NROWS * D];      // 128 MB
__device__ float g_p[NROWS];
__device__ int   g_pos[NROWS];
__device__ int   g_cnt[BATCH];
__device__ float g_bsum[BATCH * 2];
__device__ int   g_flag_cnt;
__device__ int   g_flagr[FLAG_CAP];
__device__ float g_flagrs[FLAG_CAP];

// ============================ helpers ============================
__device__ __forceinline__ uint32_t smem_u32(const void* p) {
    uint32_t a;
    asm("{ .reg .u64 t; cvta.to.shared.u64 t, %1; cvt.u32.u64 %0, t; }" : "=r"(a) : "l"(p));
    return a;
}
__device__ __forceinline__ float tf32r(float x) {
    uint32_t u;
    asm("cvt.rna.tf32.f32 %0, %1;" : "=r"(u) : "f"(x));
    return __uint_as_float(u);
}
__device__ __forceinline__ void cpasync16(uint32_t daddr, const void* gp) {
    asm volatile("cp.async.cg.shared.global [%0], [%1], 16;" :: "r"(daddr), "l"(gp) : "memory");
}
__device__ __forceinline__ void mma_tf32(float* c, const uint32_t* a, const uint32_t* b) {
    asm volatile(
        "mma.sync.aligned.m16n8k8.row.col.f32.tf32.tf32.f32 "
        "{%0,%1,%2,%3}, {%4,%5,%6,%7}, {%8,%9}, {%0,%1,%2,%3};"
        : "+f"(c[0]), "+f"(c[1]), "+f"(c[2]), "+f"(c[3])
        : "r"(a[0]), "r"(a[1]), "r"(a[2]), "r"(a[3]), "r"(b[0]), "r"(b[1]));
}

// ============================ Kernel 0: zero flag counter ============================
__global__ void zero_kernel() { g_flag_cnt = 0; }

// ============================ Kernel 1: tf32-round x and W ============================
// i < NX4: x float4 -> g_xc.  Else W float4 (Wq then Wk) -> g_Wc (stacked rows).
__global__ __launch_bounds__(256)
void cvt_kernel(const float* __restrict__ x,
                const float* __restrict__ Wq, const float* __restrict__ Wk) {
    size_t i = (size_t)blockIdx.x * 256 + threadIdx.x;
    if (i >= CVT_TOTAL) return;
    float4 v; float* dst;
    if (i < NX4) {
        v = ((const float4*)x)[i];
        dst = g_xc + i * 4;
    } else {
        size_t j = i - NX4;                             // 0 .. 131071
        if (j < 65536) v = ((const float4*)Wq)[j];
        else           v = ((const float4*)Wk)[j - 65536];
        dst = g_Wc + j * 4;
    }
    v.x = tf32r(v.x); v.y = tf32r(v.y); v.z = tf32r(v.z); v.w = tf32r(v.w);
    *(float4*)dst = v;
}

// ============================ Kernel 2: TF32 mma.sync GEMM ============================
// C[65536, 1024] = xc @ Wc^T; cols 0..511 -> g_Q, 512..1023 -> g_K.
// CTA tile 128x128, 8 warps as 4(m) x 2(n), warp tile 32x64. KC=16, 3-stage cp.async.
__global__ __launch_bounds__(256, 2)
void gemm_kernel() {
    extern __shared__ float sm[];
    const int tid  = threadIdx.x;
    const int w    = tid >> 5, lane = tid & 31;
    const int wm   = w >> 1, wn = w & 1;
    const int g    = lane >> 2, t = lane & 3;
    const int m0   = blockIdx.y * 128;
    const int n0   = blockIdx.x * 128;

    float acc[2][8][4];
    #pragma unroll
    for (int mi = 0; mi < 2; mi++)
        #pragma unroll
        for (int ni = 0; ni < 8; ni++)
            #pragma unroll
            for (int r = 0; r < 4; r++) acc[mi][ni][r] = 0.f;

    const uint32_t smu = smem_u32(sm);

    // stage loader: stage ks -> slot
    auto issue = [&](int ks, int slot) {
        const uint32_t sb = smu + (uint32_t)slot * SLOT_F * 4;
        const int k0 = ks * KC;
        #pragma unroll
        for (int h = 0; h < 2; h++) {
            int c = h * 256 + tid;               // 0..511
            int row = c >> 2, c4 = c & 3;
            // A: x rows m0..m0+127
            cpasync16(sb + (uint32_t)(row * SA + c4 * 4) * 4,
                      g_xc + (size_t)(m0 + row) * D + k0 + c4 * 4);
            // B: W rows n0..n0+127
            cpasync16(sb + (uint32_t)(128 * SA + row * SA + c4 * 4) * 4,
                      g_Wc + (size_t)(n0 + row) * D + k0 + c4 * 4);
        }
        asm volatile("cp.async.commit_group;" ::: "memory");
    };

    issue(0, 0);
    issue(1, 1);

    for (int s = 0; s < NSTG; s++) {
        if (s + 2 < NSTG) issue(s + 2, (s + 2) % 3);
        else asm volatile("cp.async.commit_group;" ::: "memory");
        asm volatile("cp.async.wait_group 2;" ::: "memory");
        __syncthreads();

        const float* As = sm + (s % 3) * SLOT_F;
        const float* Bs = As + 128 * SA;

        #pragma unroll
        for (int k8 = 0; k8 < 2; k8++) {
            const int kk = k8 * 8;
            uint32_t a[2][4];
            #pragma unroll
            for (int mi = 0; mi < 2; mi++) {
                int r0 = wm * 32 + mi * 16 + g;
                a[mi][0] = __float_as_uint(As[(r0    ) * SA + kk + t    ]);
                a[mi][1] = __float_as_uint(As[(r0 + 8) * SA + kk + t    ]);
                a[mi][2] = __float_as_uint(As[(r0    ) * SA + kk + t + 4]);
                a[mi][3] = __float_as_uint(As[(r0 + 8) * SA + kk + t + 4]);
            }
            uint32_t b[8][2];
            #pragma unroll
            for (int ni = 0; ni < 8; ni++) {
                int e = wn * 64 + ni * 8 + g;
                b[ni][0] = __float_as_uint(Bs[e * SA + kk + t    ]);
                b[ni][1] = __float_as_uint(Bs[e * SA + kk + t + 4]);
            }
            #pragma unroll
            for (int mi = 0; mi < 2; mi++)
                #pragma unroll
                for (int ni = 0; ni < 8; ni++)
                    mma_tf32(acc[mi][ni], a[mi], b[ni]);
        }
        __syncthreads();
    }

    // epilogue: cols <512 -> Q, >=512 -> K (whole CTA is one side; 512 % 128 == 0)
    float* dst = (n0 < 512) ? g_Q : g_K;
    const int col0 = (n0 & 511) + wn * 64;
    #pragma unroll
    for (int mi = 0; mi < 2; mi++) {
        int row = m0 + wm * 32 + mi * 16 + g;
        #pragma unroll
        for (int ni = 0; ni < 8; ni++) {
            int col = col0 + ni * 8 + 2 * t;
            *(float2*)(dst + (size_t)row * D + col) =
                make_float2(acc[mi][ni][0], acc[mi][ni][1]);
            *(float2*)(dst + (size_t)(row + 8) * D + col) =
                make_float2(acc[mi][ni][2], acc[mi][ni][3]);
        }
    }
}

// ============================ Kernel 3: cos / p / flag ============================
__global__ __launch_bounds__(256)
void cos_kernel() {
    const int warp = threadIdx.x >> 5, lane = threadIdx.x & 31;
    const int r = blockIdx.x * 8 + warp;
    const int l = r & (LSEQ - 1);
    const int rp = (l == 0) ? r : r - 1;
    const float4* q4 = (const float4*)(g_Q + (size_t)r  * D);
    const float4* k4 = (const float4*)(g_K + (size_t)rp * D);
    float num = 0.f, nq = 0.f, nk = 0.f;
    #pragma unroll
    for (int j = 0; j < 4; j++) {
        float4 a = q4[lane * 4 + j];
        float4 b = k4[lane * 4 + j];
        num += a.x*b.x + a.y*b.y + a.z*b.z + a.w*b.w;
        nq  += a.x*a.x + a.y*a.y + a.z*a.z + a.w*a.w;
        nk  += b.x*b.x + b.y*b.y + b.z*b.z + b.w*b.w;
    }
    #pragma unroll
    for (int m = 16; m > 0; m >>= 1) {
        num += __shfl_xor_sync(0xffffffffu, num, m);
        nq  += __shfl_xor_sync(0xffffffffu, nq,  m);
        nk  += __shfl_xor_sync(0xffffffffu, nk,  m);
    }
    if (lane == 0) {
        float rs = rsqrtf(nq * nk);
        float cs = num * rs;
        float p = fminf(fmaxf(0.5f * (1.f - cs), 0.f), 1.f);
        if (l == 0) p = 1.f;
        g_p[r] = p;
        if (l != 0 && fabsf(cs) < 1e-4f) {
            int i = atomicAdd(&g_flag_cnt, 1);
            if (i < FLAG_CAP) { g_flagr[i] = r; g_flagrs[i] = rs; }
        }
    }
}

// ============================ Kernel 4: exact fp32 recompute for flagged rows ======
__global__ __launch_bounds__(256)
void fix_kernel(const float* __restrict__ x,
                const float* __restrict__ Wq, const float* __restrict__ Wk) {
    __shared__ float4 xr[128], xp[128];
    __shared__ float  red[256];
    const int tid = threadIdx.x;
    int cnt = g_flag_cnt; if (cnt > FLAG_CAP) cnt = FLAG_CAP;
    for (int i = blockIdx.x; i < cnt; i += gridDim.x) {
        const int r = g_flagr[i];          // l != 0 guaranteed
        if (tid < 128)       xr[tid]       = ((const float4*)(x + (size_t)r * D))[tid];
        else                 xp[tid - 128] = ((const float4*)(x + (size_t)(r - 1) * D))[tid - 128];
        __syncthreads();
        float accv = 0.f;
        for (int e = tid; e < D; e += 256) {
            const float4* wq = (const float4*)(Wq + (size_t)e * D);
            const float4* wk = (const float4*)(Wk + (size_t)e * D);
            float q = 0.f, k = 0.f;
            #pragma unroll 8
            for (int d4 = 0; d4 < 128; d4++) {
                float4 a = wq[d4], bx = xr[d4];
                q += a.x*bx.x + a.y*bx.y + a.z*bx.z + a.w*bx.w;
                float4 c = wk[d4], px = xp[d4];
                k += c.x*px.x + c.y*px.y + c.z*px.z + c.w*px.w;
            }
            accv += q * k;
        }
        red[tid] = accv;
        __syncthreads();
        for (int o = 128; o > 0; o >>= 1) { if (tid < o) red[tid] += red[tid + o]; __syncthreads(); }
        if (tid == 0) {
            g_p[r] = fminf(fmaxf(0.5f * (1.f - red[0] * g_flagrs[i]), 0.f), 1.f);
        }
        __syncthreads();
    }
}

// ============================ Kernel 5: per-batch scan ============================
__global__ __launch_bounds__(256)
void scan_kernel(float* __restrict__ out) {
    const int b   = blockIdx.x;
    const int tid = threadIdx.x;
    const int PER = LSEQ / 256;            // 32
    const int base = b * LSEQ + tid * PER;

    __shared__ int   sInt[256];
    __shared__ float sF[256];

    float pv[32];
    unsigned bits = 0;
    int localsum = 0;
    float psum = 0.f;

    #pragma unroll
    for (int u = 0; u < PER; u++) {
        int r = base + u;
        float p = g_p[r];
        pv[u] = p;
        int h = (p >= 0.5f) ? 1 : 0;
        bits |= ((unsigned)h) << u;
        localsum += h;
        psum += p;
    }

    sInt[tid] = localsum;
    __syncthreads();
    for (int off = 1; off < 256; off <<= 1) {
        int v = (tid >= off) ? sInt[tid - off] : 0;
        __syncthreads();
        sInt[tid] += v;
        __syncthreads();
    }
    int excl  = sInt[tid] - localsum;
    int total = sInt[255];

    int run = excl;
    #pragma unroll
    for (int u = 0; u < PER; u++) {
        int r = base + u;
        float p = pv[u];
        int h = (bits >> u) & 1;
        out[OFF_P  + r] = p;
        out[OFF_BH + r] = h ? 1.0f : 0.0f;
        g_pos[r] = h ? run : -1;
        run += h;
    }

    sF[tid] = psum;
    __syncthreads();
    for (int off = 128; off > 0; off >>= 1) {
        if (tid < off) sF[tid] += sF[tid + off];
        __syncthreads();
    }
    if (tid == 0) {
        g_cnt[b] = total;
        g_bsum[b * 2 + 0] = (float)total;
        g_bsum[b * 2 + 1] = sF[0];
    }
}

// ============================ Kernel 6: scatter ============================
__global__ __launch_bounds__(128)
void scatter_kernel(const float* __restrict__ x, float* __restrict__ out) {
    const int r   = blockIdx.x;
    const int b   = r >> 13;
    const int l   = r & (LSEQ - 1);
    const int tid = threadIdx.x;

    int pos = g_pos[r];
    if (pos >= 0) {
        float4 v = reinterpret_cast<const float4*>(x + (size_t)r * D)[tid];
        size_t dst = (size_t)(b * LSEQ + pos) * D;
        reinterpret_cast<float4*>(out + OFF_COMP + dst)[tid] = v;
        if (tid == 0) out[OFF_PC + b * LSEQ + pos] = out[OFF_P + r];
    }
    int cnt = g_cnt[b];
    if (l >= cnt) {
        reinterpret_cast<float4*>(out + OFF_COMP + (size_t)r * D)[tid] =
            make_float4(0.f, 0.f, 0.f, 0.f);
        if (tid == 0) { out[OFF_PC + r] = 0.f; out[OFF_MASK + r] = 0.f; }
    } else if (tid == 0) {
        out[OFF_MASK + r] = 1.0f;
    }
}

// ============================ Kernel 7: ratio loss ============================
__global__ void loss_kernel(float* __restrict__ out) {
    float F = 0.f, G = 0.f;
    for (int b = 0; b < BATCH; b++) { F += g_bsum[b*2+0]; G += g_bsum[b*2+1]; }
    F /= (float)NROWS;
    G /= (float)NROWS;
    const float N = 6.0f;
    out[OFF_LOSS] = N / (N - 1.0f) * ((N - 1.0f) * F * G + (1.0f - F) * (1.0f - G));
}

// ============================ launch ============================
extern "C" void kernel_launch(void* const* d_in, const int* in_sizes, int n_in,
                              void* d_out, int out_size) {
    const float* x  = (const float*)d_in[0];
    const float* Wq = (const float*)d_in[1];
    const float* Wk = (const float*)d_in[2];
    float* out = (float*)d_out;

    cudaFuncSetAttribute(gemm_kernel, cudaFuncAttributeMaxDynamicSharedMemorySize, DYN_SMEM);

    zero_kernel<<<1, 1>>>();
    cvt_kernel<<<CVT_BLOCKS, 256>>>(x, Wq, Wk);
    {
        dim3 grid(8, 512);                                  // ntile x mtile
        gemm_kernel<<<grid, 256, DYN_SMEM>>>();
    }
    cos_kernel<<<NROWS / 8, 256>>>();
    fix_kernel<<<128, 256>>>(x, Wq, Wk);
    scan_kernel<<<BATCH, 256>>>(out);
    scatter_kernel<<<NROWS, 128>>>(x, out);
    loss_kernel<<<1, 1>>>(out);
}